// round 1
// baseline (speedup 1.0000x reference)
#include <cuda_runtime.h>
#include <math.h>

// Problem shape (fixed by the benchmark):
// video [B=8, C=1024, T=64, W=14, H=14] fp32
// params mu_x, mu_y, sigma_x, sigma_y: [N=3] fp32
// out [B, C*N] = einsum('bctwh,nwh->bcn', video, filters) / T
#define N_FILT 3
#define W_DIM 14
#define H_DIM 14
#define WH 196              // W*H
#define WH4 49              // WH/4
#define T_DIM 64
#define SLAB (T_DIM * WH)   // 12544 floats per (b,c)
#define SLAB4 (SLAB / 4)    // 3136 float4 per (b,c)

// Filters pre-scaled by 1/(sum+eps) * (1/T). 3*196 floats.
__device__ float g_filters[N_FILT * WH];

// ---------------------------------------------------------------------------
// Pre-kernel: compute the 3 normalized Gaussian filters (tiny, one CTA).
// ---------------------------------------------------------------------------
__global__ void filter_kernel(const float* __restrict__ mu_x,
                              const float* __restrict__ mu_y,
                              const float* __restrict__ sigma_x,
                              const float* __restrict__ sigma_y) {
    __shared__ float fraw[WH];
    __shared__ float red[256];
    const int tid = threadIdx.x;

    for (int n = 0; n < N_FILT; n++) {
        // squash params exactly as the reference does
        float mx = tanhf(mu_x[n]);
        float my = tanhf(mu_y[n]);
        float sgx = 1.0f / (1.0f + expf(-sigma_x[n]));
        float sgy = 1.0f / (1.0f + expf(-sigma_y[n]));
        float sx = expf(1.5f - 2.0f * sgx);
        float sy = expf(1.5f - 2.0f * sgy);
        float inv_x = 1.0f / (sx * sx + 1e-6f);
        float inv_y = 1.0f / (sy * sy + 1e-6f);
        float mux = (float)(W_DIM - 1) * ((mx + 1.0f) * 0.5f);
        float muy = (float)(H_DIM - 1) * ((my + 1.0f) * 0.5f);

        float val = 0.0f;
        if (tid < WH) {
            int w = tid / H_DIM;
            int h = tid - w * H_DIM;
            float dx = (float)w - mux;
            float dy = (float)h - muy;
            val = expf(-0.5f * (dx * dx * inv_x + dy * dy * inv_y));
            fraw[tid] = val;
        }
        red[tid] = val;
        __syncthreads();
        // tree reduction over 256
        for (int s = 128; s > 0; s >>= 1) {
            if (tid < s) red[tid] += red[tid + s];
            __syncthreads();
        }
        float scale = 1.0f / ((red[0] + 1e-6f) * (float)T_DIM);
        __syncthreads();
        if (tid < WH) {
            g_filters[n * WH + tid] = fraw[tid] * scale;
        }
        __syncthreads();
    }
}

// ---------------------------------------------------------------------------
// Main kernel: one CTA per (b,c). Streams the contiguous [T,W,H] slab with
// float4 loads, dots against the 3 filters staged in SMEM as float4 tiles.
// ---------------------------------------------------------------------------
__global__ __launch_bounds__(256, 8)
void pool_kernel(const float* __restrict__ video, float* __restrict__ out) {
    const int bc = blockIdx.x;
    const int tid = threadIdx.x;

    // SMEM filter tiles, as float4 for vector LDS
    __shared__ float4 fs[N_FILT][WH4];
    {
        const float4* gf = (const float4*)g_filters;  // 3*49 float4
        for (int i = tid; i < N_FILT * WH4; i += blockDim.x) {
            ((float4*)fs)[i] = gf[i];
        }
    }
    __syncthreads();

    const float4* vp = (const float4*)(video + (size_t)bc * SLAB);

    float a0 = 0.0f, a1 = 0.0f, a2 = 0.0f;

    // i steps by 256; wh4 = i % 49 tracked incrementally (256 % 49 == 11)
    int wh4 = tid % WH4;
    for (int i = tid; i < SLAB4; i += 256) {
        float4 v = __ldg(&vp[i]);
        float4 f0 = fs[0][wh4];
        float4 f1 = fs[1][wh4];
        float4 f2 = fs[2][wh4];
        a0 += v.x * f0.x + v.y * f0.y + v.z * f0.z + v.w * f0.w;
        a1 += v.x * f1.x + v.y * f1.y + v.z * f1.z + v.w * f1.w;
        a2 += v.x * f2.x + v.y * f2.y + v.z * f2.z + v.w * f2.w;
        wh4 += 11;
        if (wh4 >= WH4) wh4 -= WH4;
    }

    // warp reduction
    #pragma unroll
    for (int off = 16; off > 0; off >>= 1) {
        a0 += __shfl_xor_sync(0xFFFFFFFFu, a0, off);
        a1 += __shfl_xor_sync(0xFFFFFFFFu, a1, off);
        a2 += __shfl_xor_sync(0xFFFFFFFFu, a2, off);
    }

    __shared__ float part[8][N_FILT];
    const int wid = tid >> 5;
    const int lid = tid & 31;
    if (lid == 0) {
        part[wid][0] = a0;
        part[wid][1] = a1;
        part[wid][2] = a2;
    }
    __syncthreads();

    if (tid < N_FILT) {
        float s = 0.0f;
        #pragma unroll
        for (int w = 0; w < 8; w++) s += part[w][tid];
        out[(size_t)bc * N_FILT + tid] = s;
    }
}

// ---------------------------------------------------------------------------
extern "C" void kernel_launch(void* const* d_in, const int* in_sizes, int n_in,
                              void* d_out, int out_size) {
    const float* video   = (const float*)d_in[0];
    const float* mu_x    = (const float*)d_in[1];
    const float* mu_y    = (const float*)d_in[2];
    const float* sigma_x = (const float*)d_in[3];
    const float* sigma_y = (const float*)d_in[4];
    float* out = (float*)d_out;

    const int n_bc = in_sizes[0] / SLAB;  // B*C = 8192

    filter_kernel<<<1, 256>>>(mu_x, mu_y, sigma_x, sigma_y);
    pool_kernel<<<n_bc, 256>>>(video, out);
}

// round 2
// speedup vs baseline: 1.0871x; 1.0871x over previous
#include <cuda_runtime.h>
#include <math.h>

// Problem shape (fixed by the benchmark):
// video [B=8, C=1024, T=64, W=14, H=14] fp32
// params mu_x, mu_y, sigma_x, sigma_y: [N=3] fp32
// out [B, C*N] = einsum('bctwh,nwh->bcn', video, filters) / T
#define N_FILT 3
#define W_DIM 14
#define H_DIM 14
#define WH 196              // W*H
#define WH4 49              // WH/4
#define T_DIM 64
#define T_GROUPS 5          // time-slices per CTA thread-group
#define ACTIVE_THREADS (WH4 * T_GROUPS)  // 245
#define SLAB (T_DIM * WH)   // 12544 floats per (b,c)
#define SLAB4 (SLAB / 4)    // 3136 float4 per (b,c)

// Filters pre-scaled by 1/(sum+eps) * (1/T), stored as float4 for vector LDG.
__device__ float4 g_filt4[N_FILT * WH4];

// ---------------------------------------------------------------------------
// Pre-kernel: compute the 3 normalized Gaussian filters (tiny, one CTA).
// ---------------------------------------------------------------------------
__global__ void filter_kernel(const float* __restrict__ mu_x,
                              const float* __restrict__ mu_y,
                              const float* __restrict__ sigma_x,
                              const float* __restrict__ sigma_y) {
    __shared__ float fraw[WH];
    __shared__ float red[256];
    const int tid = threadIdx.x;
    float* gf = (float*)g_filt4;

    for (int n = 0; n < N_FILT; n++) {
        // squash params exactly as the reference does
        float mx = tanhf(mu_x[n]);
        float my = tanhf(mu_y[n]);
        float sgx = 1.0f / (1.0f + expf(-sigma_x[n]));
        float sgy = 1.0f / (1.0f + expf(-sigma_y[n]));
        float sx = expf(1.5f - 2.0f * sgx);
        float sy = expf(1.5f - 2.0f * sgy);
        float inv_x = 1.0f / (sx * sx + 1e-6f);
        float inv_y = 1.0f / (sy * sy + 1e-6f);
        float mux = (float)(W_DIM - 1) * ((mx + 1.0f) * 0.5f);
        float muy = (float)(H_DIM - 1) * ((my + 1.0f) * 0.5f);

        float val = 0.0f;
        if (tid < WH) {
            int w = tid / H_DIM;
            int h = tid - w * H_DIM;
            float dx = (float)w - mux;
            float dy = (float)h - muy;
            val = expf(-0.5f * (dx * dx * inv_x + dy * dy * inv_y));
            fraw[tid] = val;
        }
        red[tid] = val;
        __syncthreads();
        // tree reduction over 256
        for (int s = 128; s > 0; s >>= 1) {
            if (tid < s) red[tid] += red[tid + s];
            __syncthreads();
        }
        float scale = 1.0f / ((red[0] + 1e-6f) * (float)T_DIM);
        __syncthreads();
        if (tid < WH) {
            gf[n * WH + tid] = fraw[tid] * scale;
        }
        __syncthreads();
    }
}

// ---------------------------------------------------------------------------
// Main kernel: one CTA per (b,c). Each thread owns ONE spatial float4 position
// p and keeps the 3 filter float4s in registers; it strides over time steps
// t = g, g+5, ... Inner loop = 1 LDG.128 + 12 FFMA, no shared memory.
// ---------------------------------------------------------------------------
__global__ __launch_bounds__(256, 5)
void pool_kernel(const float* __restrict__ video, float* __restrict__ out) {
    const int bc = blockIdx.x;
    const int tid = threadIdx.x;

    float a0 = 0.0f, a1 = 0.0f, a2 = 0.0f;

    if (tid < ACTIVE_THREADS) {
        const int g = tid / WH4;        // time-group 0..4
        const int p = tid - g * WH4;    // spatial float4 position 0..48

        const float4 f0 = g_filt4[p];
        const float4 f1 = g_filt4[WH4 + p];
        const float4 f2 = g_filt4[2 * WH4 + p];

        const float4* vp = (const float4*)video + (size_t)bc * SLAB4 + p;

        #pragma unroll 4
        for (int t = g; t < T_DIM; t += T_GROUPS) {
            float4 v = __ldg(&vp[t * WH4]);
            a0 += v.x * f0.x + v.y * f0.y + v.z * f0.z + v.w * f0.w;
            a1 += v.x * f1.x + v.y * f1.y + v.z * f1.z + v.w * f1.w;
            a2 += v.x * f2.x + v.y * f2.y + v.z * f2.z + v.w * f2.w;
        }
    }

    // warp reduction (all 256 threads participate; inactive ones carry zeros)
    #pragma unroll
    for (int off = 16; off > 0; off >>= 1) {
        a0 += __shfl_xor_sync(0xFFFFFFFFu, a0, off);
        a1 += __shfl_xor_sync(0xFFFFFFFFu, a1, off);
        a2 += __shfl_xor_sync(0xFFFFFFFFu, a2, off);
    }

    __shared__ float part[8][N_FILT];
    const int wid = tid >> 5;
    const int lid = tid & 31;
    if (lid == 0) {
        part[wid][0] = a0;
        part[wid][1] = a1;
        part[wid][2] = a2;
    }
    __syncthreads();

    if (tid < N_FILT) {
        float s = 0.0f;
        #pragma unroll
        for (int w = 0; w < 8; w++) s += part[w][tid];
        out[(size_t)bc * N_FILT + tid] = s;
    }
}

// ---------------------------------------------------------------------------
extern "C" void kernel_launch(void* const* d_in, const int* in_sizes, int n_in,
                              void* d_out, int out_size) {
    const float* video   = (const float*)d_in[0];
    const float* mu_x    = (const float*)d_in[1];
    const float* mu_y    = (const float*)d_in[2];
    const float* sigma_x = (const float*)d_in[3];
    const float* sigma_y = (const float*)d_in[4];
    float* out = (float*)d_out;

    const int n_bc = in_sizes[0] / SLAB;  // B*C = 8192

    filter_kernel<<<1, 256>>>(mu_x, mu_y, sigma_x, sigma_y);
    pool_kernel<<<n_bc, 256>>>(video, out);
}